// round 9
// baseline (speedup 1.0000x reference)
#include <cuda_runtime.h>

#define SPECIES 4
#define POP     4096
#define DIM     16
#define NTOT    (SPECIES * POP)      // 16384
#define ISPAN   512                  // i-rows per pairwise block (128 thr x 4)
#define JCHUNK  128
#define JSPLIT  (POP / JCHUNK)       // 32
#define NSTEPS  4

#define LBV (-4.0f)
#define UBV (4.0f)
#define LOG2E 1.44269504088896340736f
#define TWOPI 6.283185307179586f

// ---------------- device scratch ----------------
__device__ float  g_xA[NTOT * DIM];     // original-order positions (post-update)
__device__ float  g_xS[NTOT * DIM];     // sorted-order positions
__device__ float  g_cost[NTOT];         // cost, original order
__device__ int    g_perm[NTOT];         // sorted slot -> original p (within species)
__device__ float2 g_scS[NTOT];          // sorted: (-LOG2E*sq, cost)
__device__ float  g_part[JSPLIT * 17 * NTOT];

// ---------------- f32x2 helpers ----------------
__device__ __forceinline__ unsigned long long pack2(float lo, float hi) {
    unsigned long long r;
    asm("mov.b64 %0, {%1, %2};" : "=l"(r) : "f"(lo), "f"(hi));
    return r;
}
__device__ __forceinline__ void unpack2(unsigned long long v, float& lo, float& hi) {
    asm("mov.b64 {%0, %1}, %2;" : "=f"(lo), "=f"(hi) : "l"(v));
}
#define FMA2(d, a, b, c) \
    asm("fma.rn.f32x2 %0, %1, %2, %3;" : "=l"(d) : "l"(a), "l"(b), "l"(c))
#define MUL2(d, a, b) \
    asm("mul.rn.f32x2 %0, %1, %2;" : "=l"(d) : "l"(a), "l"(b))
#define ADD2(d, a, b) \
    asm("add.rn.f32x2 %0, %1, %2;" : "=l"(d) : "l"(a), "l"(b))

// ---------------- monotone float->u32 encode/decode ----------------
__device__ __forceinline__ unsigned int enc_f(float c) {
    unsigned int cb = __float_as_uint(c);
    return (cb & 0x80000000u) ? ~cb : (cb | 0x80000000u);
}
__device__ __forceinline__ float dec_f(unsigned int e) {
    unsigned int cb = (e & 0x80000000u) ? (e & 0x7fffffffu) : ~e;
    return __uint_as_float(cb);
}

// ---------------- step-0 cost from raw input ----------------
__global__ void cost_kernel(const float* __restrict__ src) {
    int idx = blockIdx.x * blockDim.x + threadIdx.x;
    if (idx >= NTOT) return;
    const float4* xp = reinterpret_cast<const float4*>(src + (size_t)idx * DIM);
    float cost = 10.0f * (float)DIM;
#pragma unroll
    for (int u = 0; u < 4; ++u) {
        float4 xv = xp[u];
        float xs[4] = {xv.x, xv.y, xv.z, xv.w};
#pragma unroll
        for (int t = 0; t < 4; ++t)
            cost += xs[t] * xs[t] - 10.0f * cosf(TWOPI * xs[t]);
    }
    g_cost[idx] = cost;
}

// ---------------- rank sort: 8-way split scan + fused scatter ----------------
__global__ __launch_bounds__(256) void ranksort_kernel(const float* __restrict__ src) {
    __shared__ unsigned long long skey[POP];   // 32 KB
    const int s   = blockIdx.x >> 7;                 // / (POP/32)
    const int blk = blockIdx.x & 127;
    const int eL  = blk * 32 + (threadIdx.x >> 3);   // species-local element
    const int seg = threadIdx.x & 7;

    for (int t = threadIdx.x; t < POP; t += 256) {
        unsigned int ec = enc_f(g_cost[s * POP + t]);
        skey[t] = ((unsigned long long)ec << 32) | (unsigned int)t;
    }
    __syncthreads();

    const unsigned long long kme = skey[eL];

    int r0 = 0, r1 = 0;
    const uint4* k4 = reinterpret_cast<const uint4*>(skey);
#pragma unroll 8
    for (int t = 0; t < 256; ++t) {
        uint4 v = k4[t * 8 + seg];
        unsigned long long k0 = ((unsigned long long)v.y << 32) | v.x;
        unsigned long long k1 = ((unsigned long long)v.w << 32) | v.z;
        r0 += (int)(k0 < kme);
        r1 += (int)(k1 < kme);
    }
    int rank = r0 + r1;
    rank += __shfl_xor_sync(0xffffffffu, rank, 1);
    rank += __shfl_xor_sync(0xffffffffu, rank, 2);
    rank += __shfl_xor_sync(0xffffffffu, rank, 4);

    int r = s * POP + rank;
    float2 xv = *reinterpret_cast<const float2*>(src + (size_t)(s * POP + eL) * DIM + 2 * seg);
    *reinterpret_cast<float2*>(g_xS + (size_t)r * DIM + 2 * seg) = xv;
    float sq = fmaf(xv.x, xv.x, xv.y * xv.y);
    sq += __shfl_xor_sync(0xffffffffu, sq, 1);
    sq += __shfl_xor_sync(0xffffffffu, sq, 2);
    sq += __shfl_xor_sync(0xffffffffu, sq, 4);
    if (seg == 0) {
        g_perm[r] = eL;
        g_scS[r] = make_float2(-LOG2E * sq, dec_f((unsigned int)(kme >> 32)));
    }
}

// ---------------- pairwise body: rows m = M0..3 ----------------
template<int M0>
__device__ __forceinline__ void pw_rows(const float* s_x, const float2* s_sc,
                                        int ibase, int tid, int by) {
    unsigned long long xi[4][8];
    float ai[4], ci[4];
#pragma unroll
    for (int m = M0; m < 4; ++m) {
        int ig = ibase + 128 * m + tid;
        const ulonglong2* xp = reinterpret_cast<const ulonglong2*>(g_xS + (size_t)ig * DIM);
#pragma unroll
        for (int q = 0; q < 4; ++q) {
            ulonglong2 v = xp[q];
            xi[m][2 * q] = v.x; xi[m][2 * q + 1] = v.y;
        }
        float2 sc = g_scS[ig];
        ai[m] = 1.0f + sc.x;
        ci[m] = sc.y;
    }

    unsigned long long acc[4][8];
    const unsigned long long z2 = pack2(0.0f, 0.0f);
    float ws[4];
#pragma unroll
    for (int m = M0; m < 4; ++m) {
        ws[m] = 0.0f;
#pragma unroll
        for (int q = 0; q < 8; ++q) acc[m][q] = z2;
    }

#pragma unroll 2
    for (int jj = 0; jj < JCHUNK; ++jj) {
        const ulonglong2* xjv = reinterpret_cast<const ulonglong2*>(s_x + jj * DIM);
        ulonglong2 va = xjv[0];
        ulonglong2 vb = xjv[1];
        ulonglong2 vc = xjv[2];
        ulonglong2 vd = xjv[3];
        float2 scj = s_sc[jj];

#pragma unroll
        for (int m = M0; m < 4; ++m) {
            unsigned long long dp0, dp1;
            MUL2(dp0, xi[m][0], va.x);
            MUL2(dp1, xi[m][1], va.y);
            FMA2(dp0, xi[m][2], vb.x, dp0);
            FMA2(dp1, xi[m][3], vb.y, dp1);
            FMA2(dp0, xi[m][4], vc.x, dp0);
            FMA2(dp1, xi[m][5], vc.y, dp1);
            FMA2(dp0, xi[m][6], vd.x, dp0);
            FMA2(dp1, xi[m][7], vd.y, dp1);
            unsigned long long dps;
            ADD2(dps, dp0, dp1);
            float a0, a1;
            unpack2(dps, a0, a1);
            float t = fmaf(a0 + a1, 2.0f * LOG2E, ai[m] + scj.x);
            float w;
            asm("ex2.approx.f32 %0, %1;" : "=f"(w) : "f"(t));
            w = (ci[m] > scj.y) ? w : 0.0f;
            unsigned long long w2 = pack2(w, w);
            FMA2(acc[m][0], w2, va.x, acc[m][0]);
            FMA2(acc[m][1], w2, va.y, acc[m][1]);
            FMA2(acc[m][2], w2, vb.x, acc[m][2]);
            FMA2(acc[m][3], w2, vb.y, acc[m][3]);
            FMA2(acc[m][4], w2, vc.x, acc[m][4]);
            FMA2(acc[m][5], w2, vc.y, acc[m][5]);
            FMA2(acc[m][6], w2, vd.x, acc[m][6]);
            FMA2(acc[m][7], w2, vd.y, acc[m][7]);
            ws[m] += w;
        }
    }

    float* base = g_part + (size_t)by * 17 * NTOT;
#pragma unroll
    for (int m = M0; m < 4; ++m) {
        int ig = ibase + 128 * m + tid;
#pragma unroll
        for (int q = 0; q < 8; ++q) {
            float lo, hi;
            unpack2(acc[m][q], lo, hi);
            base[(2 * q) * NTOT + ig]     = lo;
            base[(2 * q + 1) * NTOT + ig] = hi;
        }
        base[16 * NTOT + ig] = ws[m];
    }
}

// ---------------- pairwise kernel: grid (8, 32, 4), block 128 ----------------
__global__ __launch_bounds__(128, 2) void pairwise_kernel() {
    const int bx = blockIdx.x, by = blockIdx.y, s = blockIdx.z;
    int m0 = by - 4 * bx;
    if (m0 > 3) return;                 // chunk entirely above all rows
    if (m0 < 0) m0 = 0;

    __shared__ float  s_x[JCHUNK * DIM];   // 8 KB
    __shared__ float2 s_sc[JCHUNK];        // 1 KB

    const int j0 = s * POP + by * JCHUNK;
    {
        const float4* src = reinterpret_cast<const float4*>(g_xS + (size_t)j0 * DIM);
        float4* dst = reinterpret_cast<float4*>(s_x);
#pragma unroll
        for (int t = threadIdx.x; t < (JCHUNK * DIM) / 4; t += 128)
            dst[t] = src[t];
        if (threadIdx.x < JCHUNK) s_sc[threadIdx.x] = g_scS[j0 + threadIdx.x];
    }
    __syncthreads();

    const int ibase = s * POP + bx * ISPAN;
    switch (m0) {
        case 0: pw_rows<0>(s_x, s_sc, ibase, threadIdx.x, by); break;
        case 1: pw_rows<1>(s_x, s_sc, ibase, threadIdx.x, by); break;
        case 2: pw_rows<2>(s_x, s_sc, ibase, threadIdx.x, by); break;
        default: pw_rows<3>(s_x, s_sc, ibase, threadIdx.x, by); break;
    }
}

// ---------------- update: 8 threads per firefly (2 dims each) ----------------
__global__ __launch_bounds__(256) void update_kernel(float* __restrict__ xout,
                                                     const float* __restrict__ noise_step,
                                                     float alpha, int do_mix) {
    int gid = blockIdx.x * 256 + threadIdx.x;   // 8*NTOT threads
    int r = gid >> 3;                            // sorted slot
    int q = gid & 7;                             // dim pair index
    int s  = r / POP;
    int rl = r % POP;
    int nch = rl / 128 + 1;                      // chunks actually written for this row

    int p = g_perm[r];
    int orig = s * POP + p;
    int ds = (do_mix && p >= POP / 2) ? ((s + 1) & (SPECIES - 1)) : s;
    int didx = ds * POP + p;

    float ws = 0.0f, a0 = 0.0f, a1 = 0.0f;
#pragma unroll 4
    for (int k = 0; k < nch; ++k) {
        const float* pk = g_part + (size_t)k * 17 * NTOT + r;
        ws += pk[(size_t)16 * NTOT];
        a0 += pk[(size_t)(2 * q) * NTOT];
        a1 += pk[(size_t)(2 * q + 1) * NTOT];
    }

    float2 xv = *reinterpret_cast<const float2*>(g_xS + (size_t)r * DIM + 2 * q);
    float2 nz = *reinterpret_cast<const float2*>(noise_step + (size_t)orig * DIM + 2 * q);
    const float scale = alpha * (UBV - LBV);

    float xn0 = xv.x + (a0 - ws * xv.x) + scale * (nz.x - 0.5f);
    float xn1 = xv.y + (a1 - ws * xv.y) + scale * (nz.y - 0.5f);
    xn0 = fminf(fmaxf(xn0, LBV), UBV);
    xn1 = fminf(fmaxf(xn1, LBV), UBV);
    *reinterpret_cast<float2*>(xout + (size_t)didx * DIM + 2 * q) = make_float2(xn0, xn1);

    float cost = (xn0 * xn0 - 10.0f * cosf(TWOPI * xn0))
               + (xn1 * xn1 - 10.0f * cosf(TWOPI * xn1));
#pragma unroll
    for (int m = 1; m <= 4; m <<= 1)
        cost += __shfl_xor_sync(0xffffffffu, cost, m);
    if (q == 0)
        g_cost[didx] = cost + 10.0f * (float)DIM;
}

// ---------------- launch ----------------
extern "C" void kernel_launch(void* const* d_in, const int* in_sizes, int n_in,
                              void* d_out, int out_size) {
    const float* fireflies = (const float*)d_in[0];
    const float* noise     = (const float*)d_in[1];
    float* out = (float*)d_out;

    float* xA;
    cudaGetSymbolAddress((void**)&xA, g_xA);

    dim3 pw_grid(POP / ISPAN, JSPLIT, SPECIES);   // (8, 32, 4)
    int rs_blocks = SPECIES * (POP / 32);          // 512

    cost_kernel<<<NTOT / 256, 256>>>(fireflies);

    double alpha = 0.1;
    const float* src = fireflies;
    for (int step = 0; step < NSTEPS; ++step) {
        ranksort_kernel<<<rs_blocks, 256>>>(src);
        pairwise_kernel<<<pw_grid, 128>>>();
        float* dst = (step == NSTEPS - 1) ? out : xA;
        const float* nz = noise + (size_t)step * NTOT * DIM;
        int do_mix = (step % 25 == 0) ? 1 : 0;
        update_kernel<<<NTOT * 8 / 256, 256>>>(dst, nz, (float)alpha, do_mix);
        alpha *= 0.995;
        src = xA;
    }
}

// round 10
// speedup vs baseline: 1.0252x; 1.0252x over previous
#include <cuda_runtime.h>

#define SPECIES 4
#define POP     4096
#define DIM     16
#define NTOT    (SPECIES * POP)      // 16384
#define ISPAN   256                  // i-rows per pairwise block (128 thr x 2)
#define JCHUNK  128
#define JSPLIT  (POP / JCHUNK)       // 32
#define NSTEPS  4
#define PSTRIDE 20                   // padded row stride in g_part (16 acc + wsum + pad)

#define LBV (-4.0f)
#define UBV (4.0f)
#define LOG2E 1.44269504088896340736f
#define TWOPI 6.283185307179586f

// ---------------- device scratch ----------------
__device__ float  g_xA[NTOT * DIM];     // original-order positions (post-update)
__device__ float  g_xS[NTOT * DIM];     // sorted-order positions
__device__ float  g_cost[NTOT];         // cost, original order
__device__ int    g_perm[NTOT];         // sorted slot -> original p (within species)
__device__ float2 g_scS[NTOT];          // sorted: (-LOG2E*sq, cost)
// partials: [by][row][PSTRIDE] — 16 acc dims, wsum at 16, pad
__device__ float  g_part[(size_t)JSPLIT * NTOT * PSTRIDE];

// ---------------- f32x2 helpers ----------------
__device__ __forceinline__ unsigned long long pack2(float lo, float hi) {
    unsigned long long r;
    asm("mov.b64 %0, {%1, %2};" : "=l"(r) : "f"(lo), "f"(hi));
    return r;
}
__device__ __forceinline__ void unpack2(unsigned long long v, float& lo, float& hi) {
    asm("mov.b64 {%0, %1}, %2;" : "=f"(lo), "=f"(hi) : "l"(v));
}
#define FMA2(d, a, b, c) \
    asm("fma.rn.f32x2 %0, %1, %2, %3;" : "=l"(d) : "l"(a), "l"(b), "l"(c))
#define MUL2(d, a, b) \
    asm("mul.rn.f32x2 %0, %1, %2;" : "=l"(d) : "l"(a), "l"(b))
#define ADD2(d, a, b) \
    asm("add.rn.f32x2 %0, %1, %2;" : "=l"(d) : "l"(a), "l"(b))

// ---------------- monotone float->u32 encode/decode ----------------
__device__ __forceinline__ unsigned int enc_f(float c) {
    unsigned int cb = __float_as_uint(c);
    return (cb & 0x80000000u) ? ~cb : (cb | 0x80000000u);
}
__device__ __forceinline__ float dec_f(unsigned int e) {
    unsigned int cb = (e & 0x80000000u) ? (e & 0x7fffffffu) : ~e;
    return __uint_as_float(cb);
}

// ---------------- step-0 cost from raw input ----------------
__global__ void cost_kernel(const float* __restrict__ src) {
    int idx = blockIdx.x * blockDim.x + threadIdx.x;
    if (idx >= NTOT) return;
    const float4* xp = reinterpret_cast<const float4*>(src + (size_t)idx * DIM);
    float cost = 10.0f * (float)DIM;
#pragma unroll
    for (int u = 0; u < 4; ++u) {
        float4 xv = xp[u];
        float xs[4] = {xv.x, xv.y, xv.z, xv.w};
#pragma unroll
        for (int t = 0; t < 4; ++t)
            cost += xs[t] * xs[t] - 10.0f * cosf(TWOPI * xs[t]);
    }
    g_cost[idx] = cost;
}

// ---------------- rank sort: 8-way split scan + fused scatter ----------------
__global__ __launch_bounds__(256) void ranksort_kernel(const float* __restrict__ src) {
    __shared__ unsigned long long skey[POP];   // 32 KB
    const int s   = blockIdx.x >> 7;                 // / (POP/32)
    const int blk = blockIdx.x & 127;
    const int eL  = blk * 32 + (threadIdx.x >> 3);   // species-local element
    const int seg = threadIdx.x & 7;

    for (int t = threadIdx.x; t < POP; t += 256) {
        unsigned int ec = enc_f(g_cost[s * POP + t]);
        skey[t] = ((unsigned long long)ec << 32) | (unsigned int)t;
    }
    __syncthreads();

    const unsigned long long kme = skey[eL];

    int r0 = 0, r1 = 0;
    const uint4* k4 = reinterpret_cast<const uint4*>(skey);
#pragma unroll 8
    for (int t = 0; t < 256; ++t) {
        uint4 v = k4[t * 8 + seg];
        unsigned long long k0 = ((unsigned long long)v.y << 32) | v.x;
        unsigned long long k1 = ((unsigned long long)v.w << 32) | v.z;
        r0 += (int)(k0 < kme);
        r1 += (int)(k1 < kme);
    }
    int rank = r0 + r1;
    rank += __shfl_xor_sync(0xffffffffu, rank, 1);
    rank += __shfl_xor_sync(0xffffffffu, rank, 2);
    rank += __shfl_xor_sync(0xffffffffu, rank, 4);

    int r = s * POP + rank;
    float2 xv = *reinterpret_cast<const float2*>(src + (size_t)(s * POP + eL) * DIM + 2 * seg);
    *reinterpret_cast<float2*>(g_xS + (size_t)r * DIM + 2 * seg) = xv;
    float sq = fmaf(xv.x, xv.x, xv.y * xv.y);
    sq += __shfl_xor_sync(0xffffffffu, sq, 1);
    sq += __shfl_xor_sync(0xffffffffu, sq, 2);
    sq += __shfl_xor_sync(0xffffffffu, sq, 4);
    if (seg == 0) {
        g_perm[r] = eL;
        g_scS[r] = make_float2(-LOG2E * sq, dec_f((unsigned int)(kme >> 32)));
    }
}

// ---------------- pairwise: 2 i-rows per thread, lower-triangle blocks ----------------
// grid: (POP/ISPAN, JSPLIT, SPECIES), block: 128
__global__ __launch_bounds__(128, 4) void pairwise_kernel() {
    if (blockIdx.y * JCHUNK > blockIdx.x * ISPAN + (ISPAN - 1)) return;

    __shared__ float  s_x[JCHUNK * DIM];   // 8 KB
    __shared__ float2 s_sc[JCHUNK];        // 1 KB

    const int s  = blockIdx.z;
    const int i0 = s * POP + blockIdx.x * ISPAN + threadIdx.x;
    const int i1 = i0 + 128;
    const int j0 = s * POP + blockIdx.y * JCHUNK;

    {
        const float4* src = reinterpret_cast<const float4*>(g_xS + (size_t)j0 * DIM);
        float4* dst = reinterpret_cast<float4*>(s_x);
#pragma unroll
        for (int t = threadIdx.x; t < (JCHUNK * DIM) / 4; t += 128)
            dst[t] = src[t];
        s_sc[threadIdx.x] = g_scS[j0 + threadIdx.x];
    }
    __syncthreads();

    unsigned long long xi0[8], xi1[8];
    {
        const ulonglong2* xp0 = reinterpret_cast<const ulonglong2*>(g_xS + (size_t)i0 * DIM);
        const ulonglong2* xp1 = reinterpret_cast<const ulonglong2*>(g_xS + (size_t)i1 * DIM);
#pragma unroll
        for (int q = 0; q < 4; ++q) {
            ulonglong2 v0 = xp0[q];
            ulonglong2 v1 = xp1[q];
            xi0[2 * q] = v0.x; xi0[2 * q + 1] = v0.y;
            xi1[2 * q] = v1.x; xi1[2 * q + 1] = v1.y;
        }
    }
    const float2 sci0 = g_scS[i0];
    const float2 sci1 = g_scS[i1];
    const float ai0 = 1.0f + sci0.x, ci0 = sci0.y;
    const float ai1 = 1.0f + sci1.x, ci1 = sci1.y;

    unsigned long long acc0[8], acc1[8];
    const unsigned long long zero2 = pack2(0.0f, 0.0f);
#pragma unroll
    for (int q = 0; q < 8; ++q) { acc0[q] = zero2; acc1[q] = zero2; }
    float ws0 = 0.0f, ws1 = 0.0f;

#pragma unroll 2
    for (int jj = 0; jj < JCHUNK; ++jj) {
        const ulonglong2* xjv = reinterpret_cast<const ulonglong2*>(s_x + jj * DIM);
        ulonglong2 va = xjv[0];
        ulonglong2 vb = xjv[1];
        ulonglong2 vc = xjv[2];
        ulonglong2 vd = xjv[3];
        float2 scj = s_sc[jj];

        unsigned long long pA, pB, qA, qB;
        MUL2(pA, xi0[0], va.x);  MUL2(pB, xi0[1], va.y);
        MUL2(qA, xi1[0], va.x);  MUL2(qB, xi1[1], va.y);
        FMA2(pA, xi0[2], vb.x, pA);  FMA2(pB, xi0[3], vb.y, pB);
        FMA2(qA, xi1[2], vb.x, qA);  FMA2(qB, xi1[3], vb.y, qB);
        FMA2(pA, xi0[4], vc.x, pA);  FMA2(pB, xi0[5], vc.y, pB);
        FMA2(qA, xi1[4], vc.x, qA);  FMA2(qB, xi1[5], vc.y, qB);
        FMA2(pA, xi0[6], vd.x, pA);  FMA2(pB, xi0[7], vd.y, pB);
        FMA2(qA, xi1[6], vd.x, qA);  FMA2(qB, xi1[7], vd.y, qB);

        unsigned long long sp, sq2;
        ADD2(sp, pA, pB);
        ADD2(sq2, qA, qB);
        float p0, p1, q0, q1;
        unpack2(sp, p0, p1);
        unpack2(sq2, q0, q1);
        float d0 = p0 + p1;
        float d1 = q0 + q1;

        float t0 = fmaf(d0, 2.0f * LOG2E, ai0 + scj.x);
        float t1 = fmaf(d1, 2.0f * LOG2E, ai1 + scj.x);
        float w0, w1;
        asm("ex2.approx.f32 %0, %1;" : "=f"(w0) : "f"(t0));
        asm("ex2.approx.f32 %0, %1;" : "=f"(w1) : "f"(t1));
        w0 = (ci0 > scj.y) ? w0 : 0.0f;
        w1 = (ci1 > scj.y) ? w1 : 0.0f;

        unsigned long long w20 = pack2(w0, w0);
        unsigned long long w21 = pack2(w1, w1);
        FMA2(acc0[0], w20, va.x, acc0[0]);  FMA2(acc1[0], w21, va.x, acc1[0]);
        FMA2(acc0[1], w20, va.y, acc0[1]);  FMA2(acc1[1], w21, va.y, acc1[1]);
        FMA2(acc0[2], w20, vb.x, acc0[2]);  FMA2(acc1[2], w21, vb.x, acc1[2]);
        FMA2(acc0[3], w20, vb.y, acc0[3]);  FMA2(acc1[3], w21, vb.y, acc1[3]);
        FMA2(acc0[4], w20, vc.x, acc0[4]);  FMA2(acc1[4], w21, vc.x, acc1[4]);
        FMA2(acc0[5], w20, vc.y, acc0[5]);  FMA2(acc1[5], w21, vc.y, acc1[5]);
        FMA2(acc0[6], w20, vd.x, acc0[6]);  FMA2(acc1[6], w21, vd.x, acc1[6]);
        FMA2(acc0[7], w20, vd.y, acc0[7]);  FMA2(acc1[7], w21, vd.y, acc1[7]);
        ws0 += w0;
        ws1 += w1;
    }

    // interleaved epilogue: [by][row][PSTRIDE], 16B-aligned vector stores
    {
        float* b0 = g_part + ((size_t)blockIdx.y * NTOT + i0) * PSTRIDE;
        float* b1 = g_part + ((size_t)blockIdx.y * NTOT + i1) * PSTRIDE;
        ulonglong2* v0 = reinterpret_cast<ulonglong2*>(b0);
        ulonglong2* v1 = reinterpret_cast<ulonglong2*>(b1);
#pragma unroll
        for (int q = 0; q < 4; ++q) {
            v0[q] = make_ulonglong2(acc0[2 * q], acc0[2 * q + 1]);
            v1[q] = make_ulonglong2(acc1[2 * q], acc1[2 * q + 1]);
        }
        b0[16] = ws0;
        b1[16] = ws1;
    }
}

// ---------------- update: 8 threads per firefly (2 dims each) ----------------
__global__ __launch_bounds__(256) void update_kernel(float* __restrict__ xout,
                                                     const float* __restrict__ noise_step,
                                                     float alpha, int do_mix) {
    int gid = blockIdx.x * 256 + threadIdx.x;   // 8*NTOT threads
    int r = gid >> 3;                            // sorted slot
    int q = gid & 7;                             // dim pair index
    int s  = r / POP;
    int rl = r % POP;
    int bi = rl / ISPAN;
    int nch = ((bi + 1) * ISPAN - 1) / JCHUNK + 1;

    int p = g_perm[r];
    int orig = s * POP + p;
    int ds = (do_mix && p >= POP / 2) ? ((s + 1) & (SPECIES - 1)) : s;
    int didx = ds * POP + p;

    float ws = 0.0f, a0 = 0.0f, a1 = 0.0f;
#pragma unroll 8
    for (int k = 0; k < nch; ++k) {
        const float* pk = g_part + ((size_t)k * NTOT + r) * PSTRIDE;
        float2 av = *reinterpret_cast<const float2*>(pk + 2 * q);
        ws += pk[16];
        a0 += av.x;
        a1 += av.y;
    }

    float2 xv = *reinterpret_cast<const float2*>(g_xS + (size_t)r * DIM + 2 * q);
    float2 nz = *reinterpret_cast<const float2*>(noise_step + (size_t)orig * DIM + 2 * q);
    const float scale = alpha * (UBV - LBV);

    float xn0 = xv.x + (a0 - ws * xv.x) + scale * (nz.x - 0.5f);
    float xn1 = xv.y + (a1 - ws * xv.y) + scale * (nz.y - 0.5f);
    xn0 = fminf(fmaxf(xn0, LBV), UBV);
    xn1 = fminf(fmaxf(xn1, LBV), UBV);
    *reinterpret_cast<float2*>(xout + (size_t)didx * DIM + 2 * q) = make_float2(xn0, xn1);

    float cost = (xn0 * xn0 - 10.0f * cosf(TWOPI * xn0))
               + (xn1 * xn1 - 10.0f * cosf(TWOPI * xn1));
#pragma unroll
    for (int m = 1; m <= 4; m <<= 1)
        cost += __shfl_xor_sync(0xffffffffu, cost, m);
    if (q == 0)
        g_cost[didx] = cost + 10.0f * (float)DIM;
}

// ---------------- launch ----------------
extern "C" void kernel_launch(void* const* d_in, const int* in_sizes, int n_in,
                              void* d_out, int out_size) {
    const float* fireflies = (const float*)d_in[0];
    const float* noise     = (const float*)d_in[1];
    float* out = (float*)d_out;

    float* xA;
    cudaGetSymbolAddress((void**)&xA, g_xA);

    dim3 pw_grid(POP / ISPAN, JSPLIT, SPECIES);   // (16, 32, 4)
    int rs_blocks = SPECIES * (POP / 32);          // 512

    cost_kernel<<<NTOT / 256, 256>>>(fireflies);

    double alpha = 0.1;
    const float* src = fireflies;
    for (int step = 0; step < NSTEPS; ++step) {
        ranksort_kernel<<<rs_blocks, 256>>>(src);
        pairwise_kernel<<<pw_grid, 128>>>();
        float* dst = (step == NSTEPS - 1) ? out : xA;
        const float* nz = noise + (size_t)step * NTOT * DIM;
        int do_mix = (step % 25 == 0) ? 1 : 0;
        update_kernel<<<NTOT * 8 / 256, 256>>>(dst, nz, (float)alpha, do_mix);
        alpha *= 0.995;
        src = xA;
    }
}

// round 11
// speedup vs baseline: 1.0917x; 1.0649x over previous
#include <cuda_runtime.h>

#define SPECIES 4
#define POP     4096
#define DIM     16
#define NTOT    (SPECIES * POP)      // 16384
#define ISPAN   256                  // i-rows per pairwise block (128 thr x 2)
#define JCHUNK  128
#define JSPLIT  (POP / JCHUNK)       // 32
#define NSTEPS  4
#define PSTRIDE 20                   // padded row stride in g_acc

#define LBV (-4.0f)
#define UBV (4.0f)
#define LOG2E 1.44269504088896340736f
#define TWOPI 6.283185307179586f

// ---------------- device scratch ----------------
__device__ float  g_xA[NTOT * DIM];     // original-order positions (post-update)
__device__ float  g_xS[NTOT * DIM];     // sorted-order positions
__device__ float  g_cost[NTOT];         // cost, original order
__device__ int    g_perm[NTOT];         // sorted slot -> original p (within species)
__device__ float2 g_scS[NTOT];          // sorted: (-LOG2E*sq, cost)
// accumulators: [row][PSTRIDE] — 16 acc dims, wsum at 16, pad; REDG-accumulated
__device__ float  g_acc[NTOT * PSTRIDE];

// ---------------- f32x2 helpers ----------------
__device__ __forceinline__ unsigned long long pack2(float lo, float hi) {
    unsigned long long r;
    asm("mov.b64 %0, {%1, %2};" : "=l"(r) : "f"(lo), "f"(hi));
    return r;
}
__device__ __forceinline__ void unpack2(unsigned long long v, float& lo, float& hi) {
    asm("mov.b64 {%0, %1}, %2;" : "=f"(lo), "=f"(hi) : "l"(v));
}
#define FMA2(d, a, b, c) \
    asm("fma.rn.f32x2 %0, %1, %2, %3;" : "=l"(d) : "l"(a), "l"(b), "l"(c))
#define MUL2(d, a, b) \
    asm("mul.rn.f32x2 %0, %1, %2;" : "=l"(d) : "l"(a), "l"(b))
#define ADD2(d, a, b) \
    asm("add.rn.f32x2 %0, %1, %2;" : "=l"(d) : "l"(a), "l"(b))

// ---------------- monotone float->u32 encode/decode ----------------
__device__ __forceinline__ unsigned int enc_f(float c) {
    unsigned int cb = __float_as_uint(c);
    return (cb & 0x80000000u) ? ~cb : (cb | 0x80000000u);
}
__device__ __forceinline__ float dec_f(unsigned int e) {
    unsigned int cb = (e & 0x80000000u) ? (e & 0x7fffffffu) : ~e;
    return __uint_as_float(cb);
}

// ---------------- step-0 cost from raw input ----------------
__global__ void cost_kernel(const float* __restrict__ src) {
    int idx = blockIdx.x * blockDim.x + threadIdx.x;
    if (idx >= NTOT) return;
    const float4* xp = reinterpret_cast<const float4*>(src + (size_t)idx * DIM);
    float cost = 10.0f * (float)DIM;
#pragma unroll
    for (int u = 0; u < 4; ++u) {
        float4 xv = xp[u];
        float xs[4] = {xv.x, xv.y, xv.z, xv.w};
#pragma unroll
        for (int t = 0; t < 4; ++t)
            cost += xs[t] * xs[t] - 10.0f * cosf(TWOPI * xs[t]);
    }
    g_cost[idx] = cost;
}

// ---------------- rank sort: 8-way split scan + fused scatter + acc zeroing ----------------
__global__ __launch_bounds__(256) void ranksort_kernel(const float* __restrict__ src) {
    __shared__ unsigned long long skey[POP];   // 32 KB
    const int s   = blockIdx.x >> 7;                 // / (POP/32)
    const int blk = blockIdx.x & 127;
    const int eL  = blk * 32 + (threadIdx.x >> 3);   // species-local element
    const int seg = threadIdx.x & 7;

    // zero the accumulator array (pairwise REDs into it after this kernel)
    {
        int zid = blockIdx.x * 256 + threadIdx.x;    // 131072 threads
        if (zid < (NTOT * PSTRIDE) / 4)
            reinterpret_cast<float4*>(g_acc)[zid] =
                make_float4(0.0f, 0.0f, 0.0f, 0.0f);
    }

    for (int t = threadIdx.x; t < POP; t += 256) {
        unsigned int ec = enc_f(g_cost[s * POP + t]);
        skey[t] = ((unsigned long long)ec << 32) | (unsigned int)t;
    }
    __syncthreads();

    const unsigned long long kme = skey[eL];

    int r0 = 0, r1 = 0;
    const uint4* k4 = reinterpret_cast<const uint4*>(skey);
#pragma unroll 8
    for (int t = 0; t < 256; ++t) {
        uint4 v = k4[t * 8 + seg];
        unsigned long long k0 = ((unsigned long long)v.y << 32) | v.x;
        unsigned long long k1 = ((unsigned long long)v.w << 32) | v.z;
        r0 += (int)(k0 < kme);
        r1 += (int)(k1 < kme);
    }
    int rank = r0 + r1;
    rank += __shfl_xor_sync(0xffffffffu, rank, 1);
    rank += __shfl_xor_sync(0xffffffffu, rank, 2);
    rank += __shfl_xor_sync(0xffffffffu, rank, 4);

    int r = s * POP + rank;
    float2 xv = *reinterpret_cast<const float2*>(src + (size_t)(s * POP + eL) * DIM + 2 * seg);
    *reinterpret_cast<float2*>(g_xS + (size_t)r * DIM + 2 * seg) = xv;
    float sq = fmaf(xv.x, xv.x, xv.y * xv.y);
    sq += __shfl_xor_sync(0xffffffffu, sq, 1);
    sq += __shfl_xor_sync(0xffffffffu, sq, 2);
    sq += __shfl_xor_sync(0xffffffffu, sq, 4);
    if (seg == 0) {
        g_perm[r] = eL;
        g_scS[r] = make_float2(-LOG2E * sq, dec_f((unsigned int)(kme >> 32)));
    }
}

// ---------------- pairwise: 2 i-rows per thread, lower-triangle blocks ----------------
// grid: (POP/ISPAN, JSPLIT, SPECIES), block: 128
__global__ __launch_bounds__(128, 4) void pairwise_kernel() {
    if (blockIdx.y * JCHUNK > blockIdx.x * ISPAN + (ISPAN - 1)) return;

    __shared__ float  s_x[JCHUNK * DIM];   // 8 KB
    __shared__ float2 s_sc[JCHUNK];        // 1 KB

    const int s  = blockIdx.z;
    const int i0 = s * POP + blockIdx.x * ISPAN + threadIdx.x;
    const int i1 = i0 + 128;
    const int j0 = s * POP + blockIdx.y * JCHUNK;

    {
        const float4* src = reinterpret_cast<const float4*>(g_xS + (size_t)j0 * DIM);
        float4* dst = reinterpret_cast<float4*>(s_x);
#pragma unroll
        for (int t = threadIdx.x; t < (JCHUNK * DIM) / 4; t += 128)
            dst[t] = src[t];
        s_sc[threadIdx.x] = g_scS[j0 + threadIdx.x];
    }
    __syncthreads();

    unsigned long long xi0[8], xi1[8];
    {
        const ulonglong2* xp0 = reinterpret_cast<const ulonglong2*>(g_xS + (size_t)i0 * DIM);
        const ulonglong2* xp1 = reinterpret_cast<const ulonglong2*>(g_xS + (size_t)i1 * DIM);
#pragma unroll
        for (int q = 0; q < 4; ++q) {
            ulonglong2 v0 = xp0[q];
            ulonglong2 v1 = xp1[q];
            xi0[2 * q] = v0.x; xi0[2 * q + 1] = v0.y;
            xi1[2 * q] = v1.x; xi1[2 * q + 1] = v1.y;
        }
    }
    const float2 sci0 = g_scS[i0];
    const float2 sci1 = g_scS[i1];
    const float ai0 = 1.0f + sci0.x, ci0 = sci0.y;
    const float ai1 = 1.0f + sci1.x, ci1 = sci1.y;

    unsigned long long acc0[8], acc1[8];
    const unsigned long long zero2 = pack2(0.0f, 0.0f);
#pragma unroll
    for (int q = 0; q < 8; ++q) { acc0[q] = zero2; acc1[q] = zero2; }
    float ws0 = 0.0f, ws1 = 0.0f;

#pragma unroll 2
    for (int jj = 0; jj < JCHUNK; ++jj) {
        const ulonglong2* xjv = reinterpret_cast<const ulonglong2*>(s_x + jj * DIM);
        ulonglong2 va = xjv[0];
        ulonglong2 vb = xjv[1];
        ulonglong2 vc = xjv[2];
        ulonglong2 vd = xjv[3];
        float2 scj = s_sc[jj];

        unsigned long long pA, pB, qA, qB;
        MUL2(pA, xi0[0], va.x);  MUL2(pB, xi0[1], va.y);
        MUL2(qA, xi1[0], va.x);  MUL2(qB, xi1[1], va.y);
        FMA2(pA, xi0[2], vb.x, pA);  FMA2(pB, xi0[3], vb.y, pB);
        FMA2(qA, xi1[2], vb.x, qA);  FMA2(qB, xi1[3], vb.y, qB);
        FMA2(pA, xi0[4], vc.x, pA);  FMA2(pB, xi0[5], vc.y, pB);
        FMA2(qA, xi1[4], vc.x, qA);  FMA2(qB, xi1[5], vc.y, qB);
        FMA2(pA, xi0[6], vd.x, pA);  FMA2(pB, xi0[7], vd.y, pB);
        FMA2(qA, xi1[6], vd.x, qA);  FMA2(qB, xi1[7], vd.y, qB);

        unsigned long long sp, sq2;
        ADD2(sp, pA, pB);
        ADD2(sq2, qA, qB);
        float p0, p1, q0, q1;
        unpack2(sp, p0, p1);
        unpack2(sq2, q0, q1);
        float d0 = p0 + p1;
        float d1 = q0 + q1;

        float t0 = fmaf(d0, 2.0f * LOG2E, ai0 + scj.x);
        float t1 = fmaf(d1, 2.0f * LOG2E, ai1 + scj.x);
        float w0, w1;
        asm("ex2.approx.f32 %0, %1;" : "=f"(w0) : "f"(t0));
        asm("ex2.approx.f32 %0, %1;" : "=f"(w1) : "f"(t1));
        w0 = (ci0 > scj.y) ? w0 : 0.0f;
        w1 = (ci1 > scj.y) ? w1 : 0.0f;

        unsigned long long w20 = pack2(w0, w0);
        unsigned long long w21 = pack2(w1, w1);
        FMA2(acc0[0], w20, va.x, acc0[0]);  FMA2(acc1[0], w21, va.x, acc1[0]);
        FMA2(acc0[1], w20, va.y, acc0[1]);  FMA2(acc1[1], w21, va.y, acc1[1]);
        FMA2(acc0[2], w20, vb.x, acc0[2]);  FMA2(acc1[2], w21, vb.x, acc1[2]);
        FMA2(acc0[3], w20, vb.y, acc0[3]);  FMA2(acc1[3], w21, vb.y, acc1[3]);
        FMA2(acc0[4], w20, vc.x, acc0[4]);  FMA2(acc1[4], w21, vc.x, acc1[4]);
        FMA2(acc0[5], w20, vc.y, acc0[5]);  FMA2(acc1[5], w21, vc.y, acc1[5]);
        FMA2(acc0[6], w20, vd.x, acc0[6]);  FMA2(acc1[6], w21, vd.x, acc1[6]);
        FMA2(acc0[7], w20, vd.y, acc0[7]);  FMA2(acc1[7], w21, vd.y, acc1[7]);
        ws0 += w0;
        ws1 += w1;
    }

    // epilogue: vector reductions into the global accumulator
    {
        float* b0 = g_acc + (size_t)i0 * PSTRIDE;
        float* b1 = g_acc + (size_t)i1 * PSTRIDE;
#pragma unroll
        for (int q = 0; q < 4; ++q) {
            float a, b, c, d;
            unpack2(acc0[2 * q], a, b);
            unpack2(acc0[2 * q + 1], c, d);
            asm volatile("red.global.add.v4.f32 [%0], {%1, %2, %3, %4};"
                         :: "l"(b0 + 4 * q), "f"(a), "f"(b), "f"(c), "f"(d)
                         : "memory");
            unpack2(acc1[2 * q], a, b);
            unpack2(acc1[2 * q + 1], c, d);
            asm volatile("red.global.add.v4.f32 [%0], {%1, %2, %3, %4};"
                         :: "l"(b1 + 4 * q), "f"(a), "f"(b), "f"(c), "f"(d)
                         : "memory");
        }
        asm volatile("red.global.add.f32 [%0], %1;" :: "l"(b0 + 16), "f"(ws0) : "memory");
        asm volatile("red.global.add.f32 [%0], %1;" :: "l"(b1 + 16), "f"(ws1) : "memory");
    }
}

// ---------------- update: 8 threads per firefly (2 dims each), no k-loop ----------------
__global__ __launch_bounds__(256) void update_kernel(float* __restrict__ xout,
                                                     const float* __restrict__ noise_step,
                                                     float alpha, int do_mix) {
    int gid = blockIdx.x * 256 + threadIdx.x;   // 8*NTOT threads
    int r = gid >> 3;                            // sorted slot
    int q = gid & 7;                             // dim pair index
    int s  = r / POP;

    int p = g_perm[r];
    int orig = s * POP + p;
    int ds = (do_mix && p >= POP / 2) ? ((s + 1) & (SPECIES - 1)) : s;
    int didx = ds * POP + p;

    const float* pk = g_acc + (size_t)r * PSTRIDE;
    float2 av = *reinterpret_cast<const float2*>(pk + 2 * q);
    float ws = pk[16];

    float2 xv = *reinterpret_cast<const float2*>(g_xS + (size_t)r * DIM + 2 * q);
    float2 nz = *reinterpret_cast<const float2*>(noise_step + (size_t)orig * DIM + 2 * q);
    const float scale = alpha * (UBV - LBV);

    float xn0 = xv.x + (av.x - ws * xv.x) + scale * (nz.x - 0.5f);
    float xn1 = xv.y + (av.y - ws * xv.y) + scale * (nz.y - 0.5f);
    xn0 = fminf(fmaxf(xn0, LBV), UBV);
    xn1 = fminf(fmaxf(xn1, LBV), UBV);
    *reinterpret_cast<float2*>(xout + (size_t)didx * DIM + 2 * q) = make_float2(xn0, xn1);

    float cost = (xn0 * xn0 - 10.0f * cosf(TWOPI * xn0))
               + (xn1 * xn1 - 10.0f * cosf(TWOPI * xn1));
#pragma unroll
    for (int m = 1; m <= 4; m <<= 1)
        cost += __shfl_xor_sync(0xffffffffu, cost, m);
    if (q == 0)
        g_cost[didx] = cost + 10.0f * (float)DIM;
}

// ---------------- launch ----------------
extern "C" void kernel_launch(void* const* d_in, const int* in_sizes, int n_in,
                              void* d_out, int out_size) {
    const float* fireflies = (const float*)d_in[0];
    const float* noise     = (const float*)d_in[1];
    float* out = (float*)d_out;

    float* xA;
    cudaGetSymbolAddress((void**)&xA, g_xA);

    dim3 pw_grid(POP / ISPAN, JSPLIT, SPECIES);   // (16, 32, 4)
    int rs_blocks = SPECIES * (POP / 32);          // 512

    cost_kernel<<<NTOT / 256, 256>>>(fireflies);

    double alpha = 0.1;
    const float* src = fireflies;
    for (int step = 0; step < NSTEPS; ++step) {
        ranksort_kernel<<<rs_blocks, 256>>>(src);
        pairwise_kernel<<<pw_grid, 128>>>();
        float* dst = (step == NSTEPS - 1) ? out : xA;
        const float* nz = noise + (size_t)step * NTOT * DIM;
        int do_mix = (step % 25 == 0) ? 1 : 0;
        update_kernel<<<NTOT * 8 / 256, 256>>>(dst, nz, (float)alpha, do_mix);
        alpha *= 0.995;
        src = xA;
    }
}

// round 13
// speedup vs baseline: 1.8323x; 1.6783x over previous
#include <cuda_runtime.h>
#include <cuda_bf16.h>
#include <cstdint>

#define SPECIES 4
#define POP     4096
#define DIM     16
#define NTOT    (SPECIES * POP)
#define NSTEPS  4
#define PSTRIDE 24
#define JP      8

#define LBV (-4.0f)
#define UBV (4.0f)
#define LOG2E 1.44269504088896340736f
#define TWOL  2.88539008177792680f
#define TWOPI 6.283185307179586f

// ---------------- device scratch ----------------
__device__ float  g_xA[NTOT * DIM];
__device__ float  g_xS[NTOT * DIM];
__device__ float  g_cost[NTOT];
__device__ int    g_perm[NTOT];
__device__ float2 g_scS[NTOT];          // (-LOG2E*sq_bf16, cost)
__device__ float  g_acc[NTOT * PSTRIDE];
__device__ uint4  g_xb[NTOT * 2];       // bf16 x, 32B/row

// ---------------- helpers ----------------
__device__ __forceinline__ uint32_t smem_u32(const void* p) {
    uint32_t a;
    asm("{ .reg .u64 t; cvta.to.shared.u64 t, %1; cvt.u32.u64 %0, t; }"
        : "=r"(a) : "l"(p));
    return a;
}
__device__ __forceinline__ void ldsm4(uint32_t* r, uint32_t a) {
    asm volatile("ldmatrix.sync.aligned.m8n8.x4.shared.b16 {%0,%1,%2,%3}, [%4];"
        : "=r"(r[0]), "=r"(r[1]), "=r"(r[2]), "=r"(r[3]) : "r"(a));
}
__device__ __forceinline__ void ldsm2(uint32_t* r, uint32_t a) {
    asm volatile("ldmatrix.sync.aligned.m8n8.x2.shared.b16 {%0,%1}, [%2];"
        : "=r"(r[0]), "=r"(r[1]) : "r"(a));
}
__device__ __forceinline__ void ldsm2t(uint32_t* r, uint32_t a) {
    asm volatile("ldmatrix.sync.aligned.m8n8.x2.trans.shared.b16 {%0,%1}, [%2];"
        : "=r"(r[0]), "=r"(r[1]) : "r"(a));
}
__device__ __forceinline__ void hmma(float* d, const uint32_t* a,
                                     const uint32_t* b, const float* c) {
    asm volatile("mma.sync.aligned.m16n8k16.row.col.f32.bf16.bf16.f32 "
        "{%0,%1,%2,%3}, {%4,%5,%6,%7}, {%8,%9}, {%10,%11,%12,%13};"
        : "=f"(d[0]), "=f"(d[1]), "=f"(d[2]), "=f"(d[3])
        : "r"(a[0]), "r"(a[1]), "r"(a[2]), "r"(a[3]), "r"(b[0]), "r"(b[1]),
          "f"(c[0]), "f"(c[1]), "f"(c[2]), "f"(c[3]));
}
__device__ __forceinline__ void hmma_zc(float* d, const uint32_t* a,
                                        const uint32_t* b) {
    const float z = 0.0f;
    asm volatile("mma.sync.aligned.m16n8k16.row.col.f32.bf16.bf16.f32 "
        "{%0,%1,%2,%3}, {%4,%5,%6,%7}, {%8,%9}, {%10,%10,%10,%10};"
        : "=f"(d[0]), "=f"(d[1]), "=f"(d[2]), "=f"(d[3])
        : "r"(a[0]), "r"(a[1]), "r"(a[2]), "r"(a[3]), "r"(b[0]), "r"(b[1]),
          "f"(z));
}
__device__ __forceinline__ uint32_t pack_bf(float hi, float lo) {
    uint32_t r;
    asm("cvt.rn.satfinite.bf16x2.f32 %0, %1, %2;" : "=r"(r) : "f"(hi), "f"(lo));
    return r;
}
__device__ __forceinline__ float ex2f(float x) {
    float r;
    asm("ex2.approx.f32 %0, %1;" : "=f"(r) : "f"(x));
    return r;
}
__device__ __forceinline__ unsigned int enc_f(float c) {
    unsigned int cb = __float_as_uint(c);
    return (cb & 0x80000000u) ? ~cb : (cb | 0x80000000u);
}
__device__ __forceinline__ float dec_f(unsigned int e) {
    unsigned int cb = (e & 0x80000000u) ? (e & 0x7fffffffu) : ~e;
    return __uint_as_float(cb);
}

// ---------------- step-0 cost ----------------
__global__ void cost_kernel(const float* __restrict__ src) {
    int idx = blockIdx.x * blockDim.x + threadIdx.x;
    if (idx >= NTOT) return;
    const float4* xp = reinterpret_cast<const float4*>(src + (size_t)idx * DIM);
    float cost = 10.0f * (float)DIM;
#pragma unroll
    for (int u = 0; u < 4; ++u) {
        float4 xv = xp[u];
        float xs[4] = {xv.x, xv.y, xv.z, xv.w};
#pragma unroll
        for (int t = 0; t < 4; ++t)
            cost += xs[t] * xs[t] - 10.0f * cosf(TWOPI * xs[t]);
    }
    g_cost[idx] = cost;
}

// ---------------- rank sort + scatter (fp32 + bf16) + acc zero ----------------
__global__ __launch_bounds__(256) void ranksort_kernel(const float* __restrict__ src) {
    __shared__ unsigned long long skey[POP];
    const int s   = blockIdx.x >> 7;
    const int blk = blockIdx.x & 127;
    const int eL  = blk * 32 + (threadIdx.x >> 3);
    const int seg = threadIdx.x & 7;

    {   // zero accumulators
        int zid = blockIdx.x * 256 + threadIdx.x;
        if (zid < (NTOT * PSTRIDE) / 4)
            reinterpret_cast<float4*>(g_acc)[zid] = make_float4(0.f, 0.f, 0.f, 0.f);
    }

    for (int t = threadIdx.x; t < POP; t += 256) {
        unsigned int ec = enc_f(g_cost[s * POP + t]);
        skey[t] = ((unsigned long long)ec << 32) | (unsigned int)t;
    }
    __syncthreads();

    const unsigned long long kme = skey[eL];
    int r0 = 0, r1 = 0;
    const uint4* k4 = reinterpret_cast<const uint4*>(skey);
#pragma unroll 8
    for (int t = 0; t < 256; ++t) {
        uint4 v = k4[t * 8 + seg];
        unsigned long long k0 = ((unsigned long long)v.y << 32) | v.x;
        unsigned long long k1 = ((unsigned long long)v.w << 32) | v.z;
        r0 += (int)(k0 < kme);
        r1 += (int)(k1 < kme);
    }
    int rank = r0 + r1;
    rank += __shfl_xor_sync(0xffffffffu, rank, 1);
    rank += __shfl_xor_sync(0xffffffffu, rank, 2);
    rank += __shfl_xor_sync(0xffffffffu, rank, 4);

    int r = s * POP + rank;
    float2 xv = *reinterpret_cast<const float2*>(src + (size_t)(s * POP + eL) * DIM + 2 * seg);
    *reinterpret_cast<float2*>(g_xS + (size_t)r * DIM + 2 * seg) = xv;

    __nv_bfloat16 b0 = __float2bfloat16(xv.x);
    __nv_bfloat16 b1 = __float2bfloat16(xv.y);
    __nv_bfloat162 bb; bb.x = b0; bb.y = b1;
    reinterpret_cast<__nv_bfloat162*>(g_xb)[(size_t)r * 8 + seg] = bb;

    float xb0 = __bfloat162float(b0), xb1 = __bfloat162float(b1);
    float sq = fmaf(xb0, xb0, xb1 * xb1);
    sq += __shfl_xor_sync(0xffffffffu, sq, 1);
    sq += __shfl_xor_sync(0xffffffffu, sq, 2);
    sq += __shfl_xor_sync(0xffffffffu, sq, 4);
    if (seg == 0) {
        g_perm[r] = eL;
        g_scS[r] = make_float2(-LOG2E * sq, dec_f((unsigned int)(kme >> 32)));
    }
}

// ---------------- pairwise via mma.sync bf16 ----------------
// grid (16, 8, SPECIES), 128 threads. CTA (kb,h): i-tiles {kb, 31-kb},
// j-tiles u == h (mod 8), u <= t. Warp w owns i-rows w*32..w*32+31.
__global__ __launch_bounds__(128) void pairwise_mma() {
    __shared__ __align__(16) unsigned short sXi[128 * 24];
    __shared__ __align__(16) unsigned short sXj[128 * 24];
    __shared__ float2 s_sc[128];

    const int tid  = threadIdx.x;
    const int w    = tid >> 5;
    const int lane = tid & 31;
    const int g    = lane >> 2;
    const int t4   = lane & 3;
    const int lr   = lane & 15;
    const int lc   = (lane >> 4) << 3;
    const int kb = blockIdx.x, h = blockIdx.y, s = blockIdx.z;
    const uint32_t bXi = smem_u32(sXi);
    const uint32_t bXj = smem_u32(sXj);

    for (int half = 0; half < 2; ++half) {
        const int t = half ? (31 - kb) : kb;
        if (h > t) continue;
        const int ibase = s * POP + t * 128;

        __syncthreads();
        // stage sXi: thread tid -> row tid (16 bf16, row stride 24 halves)
        {
            const uint4* src = &g_xb[(size_t)(ibase + tid) * 2];
            uint4 v0 = src[0], v1 = src[1];
            *reinterpret_cast<uint4*>(&sXi[tid * 24])     = v0;
            *reinterpret_cast<uint4*>(&sXi[tid * 24 + 8]) = v1;
        }
        __syncwarp();

        uint32_t A1[2][4];
        ldsm4(A1[0], bXi + (uint32_t)(((w * 32 + lr) * 24 + lc) * 2));
        ldsm4(A1[1], bXi + (uint32_t)(((w * 32 + 16 + lr) * 24 + lc) * 2));

        float ai[2][2], ci[2][2];
#pragma unroll
        for (int mt = 0; mt < 2; ++mt) {
            float2 sl = g_scS[ibase + w * 32 + mt * 16 + g];
            float2 sh = g_scS[ibase + w * 32 + mt * 16 + g + 8];
            ai[mt][0] = 1.0f + sl.x; ci[mt][0] = sl.y;
            ai[mt][1] = 1.0f + sh.x; ci[mt][1] = sh.y;
        }

        float D2[2][3][4];
#pragma unroll
        for (int mt = 0; mt < 2; ++mt)
#pragma unroll
            for (int n2 = 0; n2 < 3; ++n2)
#pragma unroll
                for (int e = 0; e < 4; ++e) D2[mt][n2][e] = 0.0f;

        for (int u = h; u <= t; u += JP) {
            const int jbase = s * POP + u * 128;
            __syncthreads();
            {
                const uint4* src = &g_xb[(size_t)(jbase + tid) * 2];
                uint4 v0 = src[0], v1 = src[1];
                *reinterpret_cast<uint4*>(&sXj[tid * 24])      = v0;
                *reinterpret_cast<uint4*>(&sXj[tid * 24 + 8])  = v1;
                *reinterpret_cast<uint4*>(&sXj[tid * 24 + 16]) =
                    make_uint4(0x00003F80u, 0u, 0u, 0u);   // dim16=1.0, 17-23=0
                s_sc[tid] = g_scS[jbase + tid];
            }
            __syncthreads();

#pragma unroll
            for (int c4 = 0; c4 < 4; ++c4) {
                const int j0 = c4 * 32;
                if (u == t && j0 > w * 32 + 31) break;   // warp-uniform prune

                uint32_t A2[2][2][4];
#pragma unroll
                for (int nt = 0; nt < 4; ++nt) {
                    uint32_t b1[2];
                    ldsm2(b1, bXj + (uint32_t)(((j0 + nt * 8 + (lane & 7)) * 24
                                                + ((lane >> 3) & 1) * 8) * 2));
                    float2 sc0 = s_sc[j0 + nt * 8 + 2 * t4];
                    float2 sc1 = s_sc[j0 + nt * 8 + 2 * t4 + 1];
#pragma unroll
                    for (int mt = 0; mt < 2; ++mt) {
                        float d[4];
                        hmma_zc(d, A1[mt], b1);
                        float w00 = (ci[mt][0] > sc0.y)
                                  ? ex2f(fmaf(d[0], TWOL, ai[mt][0] + sc0.x)) : 0.0f;
                        float w01 = (ci[mt][0] > sc1.y)
                                  ? ex2f(fmaf(d[1], TWOL, ai[mt][0] + sc1.x)) : 0.0f;
                        float w10 = (ci[mt][1] > sc0.y)
                                  ? ex2f(fmaf(d[2], TWOL, ai[mt][1] + sc0.x)) : 0.0f;
                        float w11 = (ci[mt][1] > sc1.y)
                                  ? ex2f(fmaf(d[3], TWOL, ai[mt][1] + sc1.x)) : 0.0f;
                        A2[mt][nt >> 1][(nt & 1) * 2 + 0] = pack_bf(w01, w00);
                        A2[mt][nt >> 1][(nt & 1) * 2 + 1] = pack_bf(w11, w10);
                    }
                }
#pragma unroll
                for (int kt = 0; kt < 2; ++kt) {
#pragma unroll
                    for (int n2 = 0; n2 < 3; ++n2) {
                        uint32_t b2[2];
                        ldsm2t(b2, bXj + (uint32_t)(((j0 + kt * 16 + lr) * 24
                                                     + n2 * 8) * 2));
                        hmma(D2[0][n2], A2[0][kt], b2, D2[0][n2]);
                        hmma(D2[1][n2], A2[1][kt], b2, D2[1][n2]);
                    }
                }
            }
        }

        // drain D2 -> g_acc (cols 0-15 attraction, 16 wsum, 17-23 zero pad)
#pragma unroll
        for (int mt = 0; mt < 2; ++mt) {
            int rl = ibase + w * 32 + mt * 16 + g;
#pragma unroll
            for (int n2 = 0; n2 < 3; ++n2) {
                int col = n2 * 8 + 2 * t4;
                float* p0 = g_acc + (size_t)rl * PSTRIDE + col;
                float* p1 = g_acc + (size_t)(rl + 8) * PSTRIDE + col;
                asm volatile("red.global.add.v2.f32 [%0], {%1, %2};"
                             :: "l"(p0), "f"(D2[mt][n2][0]), "f"(D2[mt][n2][1])
                             : "memory");
                asm volatile("red.global.add.v2.f32 [%0], {%1, %2};"
                             :: "l"(p1), "f"(D2[mt][n2][2]), "f"(D2[mt][n2][3])
                             : "memory");
            }
        }
    }
}

// ---------------- update: 8 threads per firefly ----------------
__global__ __launch_bounds__(256) void update_kernel(float* __restrict__ xout,
                                                     const float* __restrict__ noise_step,
                                                     float alpha, int do_mix) {
    int gid = blockIdx.x * 256 + threadIdx.x;
    int r = gid >> 3;
    int q = gid & 7;
    int s = r / POP;

    int p = g_perm[r];
    int orig = s * POP + p;
    int ds = (do_mix && p >= POP / 2) ? ((s + 1) & (SPECIES - 1)) : s;
    int didx = ds * POP + p;

    const float* pk = g_acc + (size_t)r * PSTRIDE;
    float2 av = *reinterpret_cast<const float2*>(pk + 2 * q);
    float ws = pk[16];

    float2 xv = *reinterpret_cast<const float2*>(g_xS + (size_t)r * DIM + 2 * q);
    float2 nz = *reinterpret_cast<const float2*>(noise_step + (size_t)orig * DIM + 2 * q);
    const float scale = alpha * (UBV - LBV);

    float xn0 = xv.x + (av.x - ws * xv.x) + scale * (nz.x - 0.5f);
    float xn1 = xv.y + (av.y - ws * xv.y) + scale * (nz.y - 0.5f);
    xn0 = fminf(fmaxf(xn0, LBV), UBV);
    xn1 = fminf(fmaxf(xn1, LBV), UBV);
    *reinterpret_cast<float2*>(xout + (size_t)didx * DIM + 2 * q) = make_float2(xn0, xn1);

    float cost = (xn0 * xn0 - 10.0f * cosf(TWOPI * xn0))
               + (xn1 * xn1 - 10.0f * cosf(TWOPI * xn1));
#pragma unroll
    for (int m = 1; m <= 4; m <<= 1)
        cost += __shfl_xor_sync(0xffffffffu, cost, m);
    if (q == 0)
        g_cost[didx] = cost + 10.0f * (float)DIM;
}

// ---------------- launch ----------------
extern "C" void kernel_launch(void* const* d_in, const int* in_sizes, int n_in,
                              void* d_out, int out_size) {
    const float* fireflies = (const float*)d_in[0];
    const float* noise     = (const float*)d_in[1];
    float* out = (float*)d_out;

    float* xA;
    cudaGetSymbolAddress((void**)&xA, g_xA);

    dim3 pw_grid(16, JP, SPECIES);          // 512 CTAs
    int rs_blocks = SPECIES * (POP / 32);   // 512

    cost_kernel<<<NTOT / 256, 256>>>(fireflies);

    double alpha = 0.1;
    const float* src = fireflies;
    for (int step = 0; step < NSTEPS; ++step) {
        ranksort_kernel<<<rs_blocks, 256>>>(src);
        pairwise_mma<<<pw_grid, 128>>>();
        float* dst = (step == NSTEPS - 1) ? out : xA;
        const float* nz = noise + (size_t)step * NTOT * DIM;
        int do_mix = (step % 25 == 0) ? 1 : 0;
        update_kernel<<<NTOT * 8 / 256, 256>>>(dst, nz, (float)alpha, do_mix);
        alpha *= 0.995;
        src = xA;
    }
}